// round 8
// baseline (speedup 1.0000x reference)
#include <cuda_runtime.h>
#include <cuda_bf16.h>
#include <cstdint>

#define BB  2
#define NN  16384
#define MM  4096
#define C1_ 128
#define C2_ 256
#define H1_ 256
#define H2_ 128

// ---------------------------------------------------------------------------
// Scratch
// ---------------------------------------------------------------------------
__device__ int3   g_idx[BB * NN];
__device__ float3 g_wts[BB * NN];
__device__ float  g_Gt[(size_t)BB * MM * H1_];   // (B, M, H1) point-major
__device__ float  g_h [(size_t)BB * H1_ * NN];   // (B, H1, N) channel-major

// ---------------------------------------------------------------------------
// kNN: 4 threads per query, FMA-only scoring (score = 0.5|b|^2 - a.b)
// ---------------------------------------------------------------------------
__device__ __forceinline__ void ins3(float d, int i,
                                     float& s0, float& s1, float& s2,
                                     int& i0, int& i1, int& i2) {
    if (d < s2) {
        if (d < s1) {
            s2 = s1; i2 = i1;
            if (d < s0) { s1 = s0; i1 = i0; s0 = d; i0 = i; }
            else        { s1 = d;  i1 = i; }
        } else { s2 = d; i2 = i; }
    }
}

__global__ void knn_kernel(const float* __restrict__ unknown,
                           const float* __restrict__ known,
                           int3* __restrict__ idx_out,
                           float3* __restrict__ wts_out)
{
    extern __shared__ float sm[];
    float* sx = sm;
    float* sy = sm + MM;
    float* sz = sm + 2 * MM;
    float* sh = sm + 3 * MM;

    const int b   = blockIdx.y;
    const int tid = threadIdx.x;

    const float* kb = known + (size_t)b * MM * 3;
    for (int i = tid; i < MM; i += blockDim.x) {
        float x = kb[i * 3 + 0], y = kb[i * 3 + 1], z = kb[i * 3 + 2];
        sx[i] = x; sy[i] = y; sz[i] = z;
        sh[i] = 0.5f * (x * x + y * y + z * z);
    }
    __syncthreads();

    const int q     = blockIdx.x * 64 + (tid >> 2);
    const int slice = tid & 3;

    const float3 a = ((const float3*)unknown)[(size_t)b * NN + q];
    const float nax = -a.x, nay = -a.y, naz = -a.z;

    float s0 = 1e30f, s1 = 1e30f, s2 = 1e30f;
    int i0 = 0, i1 = 0, i2 = 0;

    const float4* x4 = (const float4*)sx + slice * (MM / 16);
    const float4* y4 = (const float4*)sy + slice * (MM / 16);
    const float4* z4 = (const float4*)sz + slice * (MM / 16);
    const float4* h4 = (const float4*)sh + slice * (MM / 16);
    const int mbase = slice * (MM / 4);

    #pragma unroll 2
    for (int j = 0; j < MM / 16; j++) {
        float4 X = x4[j], Y = y4[j], Z = z4[j], H = h4[j];
        float t0 = fmaf(X.x, nax, fmaf(Y.x, nay, fmaf(Z.x, naz, H.x)));
        float t1 = fmaf(X.y, nax, fmaf(Y.y, nay, fmaf(Z.y, naz, H.y)));
        float t2 = fmaf(X.z, nax, fmaf(Y.z, nay, fmaf(Z.z, naz, H.z)));
        float t3 = fmaf(X.w, nax, fmaf(Y.w, nay, fmaf(Z.w, naz, H.w)));
        float m = fminf(fminf(t0, t1), fminf(t2, t3));
        if (m < s2) {
            int mb = mbase + j * 4;
            ins3(t0, mb + 0, s0, s1, s2, i0, i1, i2);
            ins3(t1, mb + 1, s0, s1, s2, i0, i1, i2);
            ins3(t2, mb + 2, s0, s1, s2, i0, i1, i2);
            ins3(t3, mb + 3, s0, s1, s2, i0, i1, i2);
        }
    }

    #pragma unroll
    for (int delta = 1; delta <= 2; delta <<= 1) {
        float a0 = __shfl_xor_sync(0xFFFFFFFF, s0, delta);
        float a1 = __shfl_xor_sync(0xFFFFFFFF, s1, delta);
        float a2 = __shfl_xor_sync(0xFFFFFFFF, s2, delta);
        int b0 = __shfl_xor_sync(0xFFFFFFFF, i0, delta);
        int b1 = __shfl_xor_sync(0xFFFFFFFF, i1, delta);
        int b2 = __shfl_xor_sync(0xFFFFFFFF, i2, delta);
        ins3(a0, b0, s0, s1, s2, i0, i1, i2);
        ins3(a1, b1, s0, s1, s2, i0, i1, i2);
        ins3(a2, b2, s0, s1, s2, i0, i1, i2);
    }

    if (slice == 0) {
        float dx, dy, dz;
        dx = sx[i0] - a.x; dy = sy[i0] - a.y; dz = sz[i0] - a.z;
        float d0 = dx * dx + dy * dy + dz * dz;
        dx = sx[i1] - a.x; dy = sy[i1] - a.y; dz = sz[i1] - a.z;
        float d1 = dx * dx + dy * dy + dz * dz;
        dx = sx[i2] - a.x; dy = sy[i2] - a.y; dz = sz[i2] - a.z;
        float d2 = dx * dx + dy * dy + dz * dz;

        float r0 = 1.0f / (sqrtf(d0) + 1e-8f);
        float r1 = 1.0f / (sqrtf(d1) + 1e-8f);
        float r2 = 1.0f / (sqrtf(d2) + 1e-8f);
        float rs = 1.0f / (r0 + r1 + r2);
        idx_out[(size_t)b * NN + q] = make_int3(i0, i1, i2);
        wts_out[(size_t)b * NN + q] = make_float3(r0 * rs, r1 * rs, r2 * rs);
    }
}

// ---------------------------------------------------------------------------
// Shared GEMM core: tile 64(O) x 128(P) x 16, 256 threads, 4x8 per thread,
// double-buffered smem. Thread (tx,ty): o = o0+ty*4+i, p = p0+tx*8+j.
// ---------------------------------------------------------------------------
#define GEMM_PROLOG_AND_LOOP(Wm, ldW, Xb, P, K)                                     \
    __shared__ float Ws[2][16][64];                                                 \
    __shared__ float Xs[2][16][128];                                                \
    const int t  = threadIdx.x;                                                     \
    const int tx = t & 15;                                                          \
    const int ty = t >> 4;                                                          \
    const int wo = t & 63, wk = (t >> 6) * 4;                                       \
    const int xk = t >> 4, xp = (t & 15) * 8;                                       \
    const float* wsrc = (Wm) + (long)(o0 + wo) * (ldW) + wk;                        \
    const float* xsrc = (Xb) + (long)xk * (P) + p0 + xp;                            \
    float acc[4][8] = {};                                                           \
    {                                                                               \
        float4 wv = *(const float4*)&wsrc[0];                                       \
        Ws[0][wk + 0][wo] = wv.x; Ws[0][wk + 1][wo] = wv.y;                         \
        Ws[0][wk + 2][wo] = wv.z; Ws[0][wk + 3][wo] = wv.w;                         \
        *(float4*)&Xs[0][xk][xp]     = *(const float4*)&xsrc[0];                    \
        *(float4*)&Xs[0][xk][xp + 4] = *(const float4*)&xsrc[4];                    \
    }                                                                               \
    __syncthreads();                                                                \
    int buf = 0;                                                                    \
    for (int k0 = 0; k0 < (K); k0 += 16) {                                          \
        const bool has_next = (k0 + 16 < (K));                                      \
        float4 wv, x0, x1;                                                          \
        if (has_next) {                                                             \
            wv = *(const float4*)&wsrc[k0 + 16];                                    \
            x0 = *(const float4*)&xsrc[(long)(k0 + 16) * (P)];                      \
            x1 = *(const float4*)&xsrc[(long)(k0 + 16) * (P) + 4];                  \
        }                                                                           \
        _Pragma("unroll")                                                           \
        for (int k = 0; k < 16; k++) {                                              \
            float a[4], bv[8];                                                      \
            *(float4*)&a[0]  = *(const float4*)&Ws[buf][k][ty * 4];                 \
            *(float4*)&bv[0] = *(const float4*)&Xs[buf][k][tx * 8];                 \
            *(float4*)&bv[4] = *(const float4*)&Xs[buf][k][tx * 8 + 4];             \
            _Pragma("unroll")                                                       \
            for (int i = 0; i < 4; i++)                                             \
                _Pragma("unroll")                                                   \
                for (int j = 0; j < 8; j++)                                         \
                    acc[i][j] = fmaf(a[i], bv[j], acc[i][j]);                       \
        }                                                                           \
        if (has_next) {                                                             \
            int nb = buf ^ 1;                                                       \
            Ws[nb][wk + 0][wo] = wv.x; Ws[nb][wk + 1][wo] = wv.y;                   \
            Ws[nb][wk + 2][wo] = wv.z; Ws[nb][wk + 3][wo] = wv.w;                   \
            *(float4*)&Xs[nb][xk][xp]     = x0;                                     \
            *(float4*)&Xs[nb][xk][xp + 4] = x1;                                     \
            __syncthreads();                                                        \
            buf = nb;                                                               \
        }                                                                           \
    }

// ---------------------------------------------------------------------------
// GEMM A: C stored point-major (P, O)   [for Gt]
// ---------------------------------------------------------------------------
__global__ void __launch_bounds__(256)
gemm_po_kernel(const float* __restrict__ Wm, int ldW,
               const float* __restrict__ X, long strideX,
               float* __restrict__ C, long strideC,
               int O, int P, int K)
{
    const float* Xb = X + (long)blockIdx.z * strideX;
    float*       Cb = C + (long)blockIdx.z * strideC;
    const int o0 = blockIdx.y * 64;
    const int p0 = blockIdx.x * 128;

    GEMM_PROLOG_AND_LOOP(Wm, ldW, Xb, P, K)

    const int ot = o0 + ty * 4;
    const int pt = p0 + tx * 8;
    #pragma unroll
    for (int j = 0; j < 8; j++) {
        float4 v = make_float4(acc[0][j], acc[1][j], acc[2][j], acc[3][j]);
        *(float4*)&Cb[(long)(pt + j) * O + ot] = v;
    }
}

// ---------------------------------------------------------------------------
// GEMM B (fused): Ut tile in regs + gather-interpolate Gt + bias + ReLU,
// stored channel-major (O, P) into h.
// ---------------------------------------------------------------------------
__global__ void __launch_bounds__(256)
gemm_fused_kernel(const float* __restrict__ Wm, int ldW,
                  const float* __restrict__ X, long strideX,
                  const float* __restrict__ Gt,
                  const int3* __restrict__ idx,
                  const float3* __restrict__ wts,
                  const float* __restrict__ b1,
                  float* __restrict__ h,
                  int O, int P, int K)
{
    const int bz = blockIdx.z;
    const float* Xb = X + (long)bz * strideX;
    const int o0 = blockIdx.y * 64;
    const int p0 = blockIdx.x * 128;

    GEMM_PROLOG_AND_LOOP(Wm, ldW, Xb, P, K)

    const int ot = o0 + ty * 4;
    const int pt = p0 + tx * 8;

    const float4 bv4 = *(const float4*)&b1[ot];
    const float* gbase = Gt + (long)bz * MM * H1_;

    float hv[4][8];
    #pragma unroll
    for (int j = 0; j < 8; j++) {
        const int n = pt + j;
        const int3   id = idx[(size_t)bz * NN + n];
        const float3 ww = wts[(size_t)bz * NN + n];
        float4 g0 = *(const float4*)&gbase[(long)id.x * H1_ + ot];
        float4 g1 = *(const float4*)&gbase[(long)id.y * H1_ + ot];
        float4 g2 = *(const float4*)&gbase[(long)id.z * H1_ + ot];
        hv[0][j] = fmaxf(acc[0][j] + ww.x * g0.x + ww.y * g1.x + ww.z * g2.x + bv4.x, 0.0f);
        hv[1][j] = fmaxf(acc[1][j] + ww.x * g0.y + ww.y * g1.y + ww.z * g2.y + bv4.y, 0.0f);
        hv[2][j] = fmaxf(acc[2][j] + ww.x * g0.z + ww.y * g1.z + ww.z * g2.z + bv4.z, 0.0f);
        hv[3][j] = fmaxf(acc[3][j] + ww.x * g0.w + ww.y * g1.w + ww.z * g2.w + bv4.w, 0.0f);
    }

    float* hb = h + (long)bz * H1_ * NN;
    #pragma unroll
    for (int i = 0; i < 4; i++) {
        *(float4*)&hb[(long)(ot + i) * NN + pt]     = *(float4*)&hv[i][0];
        *(float4*)&hb[(long)(ot + i) * NN + pt + 4] = *(float4*)&hv[i][4];
    }
}

// ---------------------------------------------------------------------------
// GEMM C: C stored (O, P) with bias + ReLU   [final output]
// ---------------------------------------------------------------------------
__global__ void __launch_bounds__(256)
gemm_op_kernel(const float* __restrict__ Wm, int ldW,
               const float* __restrict__ X, long strideX,
               float* __restrict__ C, long strideC,
               const float* __restrict__ bias,
               int O, int P, int K)
{
    const float* Xb = X + (long)blockIdx.z * strideX;
    float*       Cb = C + (long)blockIdx.z * strideC;
    const int o0 = blockIdx.y * 64;
    const int p0 = blockIdx.x * 128;

    GEMM_PROLOG_AND_LOOP(Wm, ldW, Xb, P, K)

    const int ot = o0 + ty * 4;
    const int pt = p0 + tx * 8;
    const float4 bv4 = *(const float4*)&bias[ot];
    const float bb[4] = {bv4.x, bv4.y, bv4.z, bv4.w};

    #pragma unroll
    for (int i = 0; i < 4; i++) {
        float4 v0, v1;
        v0.x = fmaxf(acc[i][0] + bb[i], 0.0f);
        v0.y = fmaxf(acc[i][1] + bb[i], 0.0f);
        v0.z = fmaxf(acc[i][2] + bb[i], 0.0f);
        v0.w = fmaxf(acc[i][3] + bb[i], 0.0f);
        v1.x = fmaxf(acc[i][4] + bb[i], 0.0f);
        v1.y = fmaxf(acc[i][5] + bb[i], 0.0f);
        v1.z = fmaxf(acc[i][6] + bb[i], 0.0f);
        v1.w = fmaxf(acc[i][7] + bb[i], 0.0f);
        *(float4*)&Cb[(long)(ot + i) * P + pt]     = v0;
        *(float4*)&Cb[(long)(ot + i) * P + pt + 4] = v1;
    }
}

// ---------------------------------------------------------------------------
// Launch
// ---------------------------------------------------------------------------
extern "C" void kernel_launch(void* const* d_in, const int* in_sizes, int n_in,
                              void* d_out, int out_size)
{
    const float* unknown      = (const float*)d_in[0];
    const float* known        = (const float*)d_in[1];
    const float* unknow_feats = (const float*)d_in[2];
    const float* known_feats  = (const float*)d_in[3];
    const float* W1           = (const float*)d_in[4];
    const float* b1           = (const float*)d_in[5];
    const float* W2           = (const float*)d_in[6];
    const float* b2           = (const float*)d_in[7];
    float* out = (float*)d_out;

    void *pGt, *pH, *pIdx, *pWts;
    cudaGetSymbolAddress(&pGt,  g_Gt);
    cudaGetSymbolAddress(&pH,   g_h);
    cudaGetSymbolAddress(&pIdx, g_idx);
    cudaGetSymbolAddress(&pWts, g_wts);

    const int knn_smem = 4 * MM * 4;  // 64KB
    cudaFuncSetAttribute(knn_kernel, cudaFuncAttributeMaxDynamicSharedMemorySize, knn_smem);

    // 1) 3-NN + weights (4 threads per query)
    knn_kernel<<<dim3(NN / 64, BB), 256, knn_smem>>>(unknown, known, (int3*)pIdx, (float3*)pWts);

    // 2) Gt[b,m,o] = sum_c W1[o,c] * known_feats[b,c,m]  (c in [0,256)), (P,O) store
    gemm_po_kernel<<<dim3(MM / 128, H1_ / 64, BB), 256>>>(
        W1, C1_ + C2_, known_feats, (long)C2_ * MM,
        (float*)pGt, (long)MM * H1_, H1_, MM, C2_);

    // 3+4) h = relu( W1b @ unknow_feats + gather-interp(Gt) + b1 ), (O,P) store
    gemm_fused_kernel<<<dim3(NN / 128, H1_ / 64, BB), 256>>>(
        W1 + C2_, C1_ + C2_, unknow_feats, (long)C1_ * NN,
        (const float*)pGt, (const int3*)pIdx, (const float3*)pWts,
        b1, (float*)pH, H1_, NN, C1_);

    // 5) out = relu(W2 @ h + b2), (O,P) store
    gemm_op_kernel<<<dim3(NN / 128, H2_ / 64, BB), 256>>>(
        W2, H1_, (const float*)pH, (long)H1_ * NN,
        out, (long)H2_ * NN, b2, H2_, NN, H1_);
}

// round 11
// speedup vs baseline: 1.9355x; 1.9355x over previous
#include <cuda_runtime.h>
#include <cuda_bf16.h>
#include <cstdint>

#define BB  2
#define NN  16384
#define MM  4096
#define C1_ 128
#define C2_ 256
#define H1_ 256
#define H2_ 128

// ---------------------------------------------------------------------------
// Scratch
// ---------------------------------------------------------------------------
__device__ int3   g_idx[BB * NN];
__device__ float3 g_wts[BB * NN];
__device__ float  g_Gt[(size_t)BB * MM * H1_];   // (B, M, H1) point-major
__device__ float  g_h [(size_t)BB * H1_ * NN];   // (B, H1, N) channel-major

// ---------------------------------------------------------------------------
// kNN (R1-proven): 1 thread per query, known points staged in 48KB smem.
// ---------------------------------------------------------------------------
__global__ void knn_kernel(const float* __restrict__ unknown,
                           const float* __restrict__ known,
                           int3* __restrict__ idx_out,
                           float3* __restrict__ wts_out)
{
    __shared__ float3 skn[MM];   // 49152B
    const int b = blockIdx.y;

    const float3* kn = (const float3*)known + (size_t)b * MM;
    for (int i = threadIdx.x; i < MM; i += blockDim.x) skn[i] = kn[i];
    __syncthreads();

    const int n = blockIdx.x * blockDim.x + threadIdx.x;
    const float3 p = ((const float3*)unknown)[(size_t)b * NN + n];

    float d0 = 1e30f, d1 = 1e30f, d2 = 1e30f;
    int   i0 = 0, i1 = 0, i2 = 0;

    #pragma unroll 4
    for (int m = 0; m < MM; m++) {
        float dx = skn[m].x - p.x;
        float dy = skn[m].y - p.y;
        float dz = skn[m].z - p.z;
        float d  = dx * dx + dy * dy + dz * dz;
        if (d < d2) {
            if (d < d1) {
                if (d < d0) { d2 = d1; i2 = i1; d1 = d0; i1 = i0; d0 = d; i0 = m; }
                else        { d2 = d1; i2 = i1; d1 = d;  i1 = m; }
            } else          { d2 = d;  i2 = m; }
        }
    }

    float r0 = 1.0f / (sqrtf(d0) + 1e-8f);
    float r1 = 1.0f / (sqrtf(d1) + 1e-8f);
    float r2 = 1.0f / (sqrtf(d2) + 1e-8f);
    float rs = 1.0f / (r0 + r1 + r2);

    idx_out[(size_t)b * NN + n] = make_int3(i0, i1, i2);
    wts_out[(size_t)b * NN + n] = make_float3(r0 * rs, r1 * rs, r2 * rs);
}

// ---------------------------------------------------------------------------
// Shared GEMM core: tile 64(O) x 128(P) x 16, 256 threads, 4x8 per thread,
// double-buffered smem, conflict-free operand maps.
// Thread (tx,ty): o rows = o0+ty*4+i;  p cols = p0+tx*4+j  and  p0+64+tx*4+j.
// W staging: row = t>>2 (coalesced 64B), cols (t&3)*4.
// ---------------------------------------------------------------------------
#define GEMM_PROLOG_AND_LOOP(Wm, ldW, Xb, P, K)                                     \
    __shared__ float Ws[2][16][64];                                                 \
    __shared__ float Xs[2][16][128];                                                \
    const int t  = threadIdx.x;                                                     \
    const int tx = t & 15;                                                          \
    const int ty = t >> 4;                                                          \
    const int wo = t >> 2, wk = (t & 3) * 4;                                        \
    const int xk = t >> 4, xp = (t & 15) * 8;                                       \
    const float* wsrc = (Wm) + (long)(o0 + wo) * (ldW) + wk;                        \
    const float* xsrc = (Xb) + (long)xk * (P) + p0 + xp;                            \
    float acc[4][8] = {};                                                           \
    {                                                                               \
        float4 wv = *(const float4*)&wsrc[0];                                       \
        Ws[0][wk + 0][wo] = wv.x; Ws[0][wk + 1][wo] = wv.y;                         \
        Ws[0][wk + 2][wo] = wv.z; Ws[0][wk + 3][wo] = wv.w;                         \
        *(float4*)&Xs[0][xk][xp]     = *(const float4*)&xsrc[0];                    \
        *(float4*)&Xs[0][xk][xp + 4] = *(const float4*)&xsrc[4];                    \
    }                                                                               \
    __syncthreads();                                                                \
    int buf = 0;                                                                    \
    for (int k0 = 0; k0 < (K); k0 += 16) {                                          \
        const bool has_next = (k0 + 16 < (K));                                      \
        float4 wv, x0, x1;                                                          \
        if (has_next) {                                                             \
            wv = *(const float4*)&wsrc[k0 + 16];                                    \
            x0 = *(const float4*)&xsrc[(long)(k0 + 16) * (P)];                      \
            x1 = *(const float4*)&xsrc[(long)(k0 + 16) * (P) + 4];                  \
        }                                                                           \
        _Pragma("unroll")                                                           \
        for (int k = 0; k < 16; k++) {                                              \
            float a[4], bv[8];                                                      \
            *(float4*)&a[0]  = *(const float4*)&Ws[buf][k][ty * 4];                 \
            *(float4*)&bv[0] = *(const float4*)&Xs[buf][k][tx * 4];                 \
            *(float4*)&bv[4] = *(const float4*)&Xs[buf][k][64 + tx * 4];            \
            _Pragma("unroll")                                                       \
            for (int i = 0; i < 4; i++)                                             \
                _Pragma("unroll")                                                   \
                for (int j = 0; j < 8; j++)                                         \
                    acc[i][j] = fmaf(a[i], bv[j], acc[i][j]);                       \
        }                                                                           \
        if (has_next) {                                                             \
            int nb = buf ^ 1;                                                       \
            Ws[nb][wk + 0][wo] = wv.x; Ws[nb][wk + 1][wo] = wv.y;                   \
            Ws[nb][wk + 2][wo] = wv.z; Ws[nb][wk + 3][wo] = wv.w;                   \
            *(float4*)&Xs[nb][xk][xp]     = x0;                                     \
            *(float4*)&Xs[nb][xk][xp + 4] = x1;                                     \
            __syncthreads();                                                        \
            buf = nb;                                                               \
        }                                                                           \
    }

// ---------------------------------------------------------------------------
// GEMM A: C stored point-major (P, O)   [for Gt]
// ---------------------------------------------------------------------------
__global__ void __launch_bounds__(256)
gemm_po_kernel(const float* __restrict__ Wm, int ldW,
               const float* __restrict__ X, long strideX,
               float* __restrict__ C, long strideC,
               int O, int P, int K)
{
    const float* Xb = X + (long)blockIdx.z * strideX;
    float*       Cb = C + (long)blockIdx.z * strideC;
    const int o0 = blockIdx.y * 64;
    const int p0 = blockIdx.x * 128;

    GEMM_PROLOG_AND_LOOP(Wm, ldW, Xb, P, K)

    const int ot  = o0 + ty * 4;
    const int ptA = p0 + tx * 4;
    const int ptB = p0 + 64 + tx * 4;
    #pragma unroll
    for (int j = 0; j < 4; j++) {
        float4 vA = make_float4(acc[0][j],     acc[1][j],     acc[2][j],     acc[3][j]);
        float4 vB = make_float4(acc[0][j + 4], acc[1][j + 4], acc[2][j + 4], acc[3][j + 4]);
        *(float4*)&Cb[(long)(ptA + j) * O + ot] = vA;
        *(float4*)&Cb[(long)(ptB + j) * O + ot] = vB;
    }
}

// ---------------------------------------------------------------------------
// GEMM B (fused): Ut tile in regs + gather-interpolate Gt + bias + ReLU,
// stored channel-major (O, P) into h.
// ---------------------------------------------------------------------------
__global__ void __launch_bounds__(256)
gemm_fused_kernel(const float* __restrict__ Wm, int ldW,
                  const float* __restrict__ X, long strideX,
                  const float* __restrict__ Gt,
                  const int3* __restrict__ idx,
                  const float3* __restrict__ wts,
                  const float* __restrict__ b1,
                  float* __restrict__ h,
                  int O, int P, int K)
{
    const int bz = blockIdx.z;
    const float* Xb = X + (long)bz * strideX;
    const int o0 = blockIdx.y * 64;
    const int p0 = blockIdx.x * 128;

    GEMM_PROLOG_AND_LOOP(Wm, ldW, Xb, P, K)

    const int ot = o0 + ty * 4;

    const float4 bv4 = *(const float4*)&b1[ot];
    const float* gbase = Gt + (long)bz * MM * H1_;

    float hv[4][8];
    #pragma unroll
    for (int jj = 0; jj < 8; jj++) {
        const int n = p0 + ((jj < 4) ? (tx * 4 + jj) : (64 + tx * 4 + jj - 4));
        const int3   id = idx[(size_t)bz * NN + n];
        const float3 ww = wts[(size_t)bz * NN + n];
        float4 g0 = *(const float4*)&gbase[(long)id.x * H1_ + ot];
        float4 g1 = *(const float4*)&gbase[(long)id.y * H1_ + ot];
        float4 g2 = *(const float4*)&gbase[(long)id.z * H1_ + ot];
        hv[0][jj] = fmaxf(acc[0][jj] + ww.x * g0.x + ww.y * g1.x + ww.z * g2.x + bv4.x, 0.0f);
        hv[1][jj] = fmaxf(acc[1][jj] + ww.x * g0.y + ww.y * g1.y + ww.z * g2.y + bv4.y, 0.0f);
        hv[2][jj] = fmaxf(acc[2][jj] + ww.x * g0.z + ww.y * g1.z + ww.z * g2.z + bv4.z, 0.0f);
        hv[3][jj] = fmaxf(acc[3][jj] + ww.x * g0.w + ww.y * g1.w + ww.z * g2.w + bv4.w, 0.0f);
    }

    float* hb = h + (long)bz * H1_ * NN;
    const int ptA = p0 + tx * 4;
    const int ptB = p0 + 64 + tx * 4;
    #pragma unroll
    for (int i = 0; i < 4; i++) {
        *(float4*)&hb[(long)(ot + i) * NN + ptA] = *(float4*)&hv[i][0];
        *(float4*)&hb[(long)(ot + i) * NN + ptB] = *(float4*)&hv[i][4];
    }
}

// ---------------------------------------------------------------------------
// GEMM C: C stored (O, P) with bias + ReLU   [final output]
// ---------------------------------------------------------------------------
__global__ void __launch_bounds__(256)
gemm_op_kernel(const float* __restrict__ Wm, int ldW,
               const float* __restrict__ X, long strideX,
               float* __restrict__ C, long strideC,
               const float* __restrict__ bias,
               int O, int P, int K)
{
    const float* Xb = X + (long)blockIdx.z * strideX;
    float*       Cb = C + (long)blockIdx.z * strideC;
    const int o0 = blockIdx.y * 64;
    const int p0 = blockIdx.x * 128;

    GEMM_PROLOG_AND_LOOP(Wm, ldW, Xb, P, K)

    const int ot  = o0 + ty * 4;
    const int ptA = p0 + tx * 4;
    const int ptB = p0 + 64 + tx * 4;
    const float4 bv4 = *(const float4*)&bias[ot];
    const float bb[4] = {bv4.x, bv4.y, bv4.z, bv4.w};

    #pragma unroll
    for (int i = 0; i < 4; i++) {
        float4 vA, vB;
        vA.x = fmaxf(acc[i][0] + bb[i], 0.0f);
        vA.y = fmaxf(acc[i][1] + bb[i], 0.0f);
        vA.z = fmaxf(acc[i][2] + bb[i], 0.0f);
        vA.w = fmaxf(acc[i][3] + bb[i], 0.0f);
        vB.x = fmaxf(acc[i][4] + bb[i], 0.0f);
        vB.y = fmaxf(acc[i][5] + bb[i], 0.0f);
        vB.z = fmaxf(acc[i][6] + bb[i], 0.0f);
        vB.w = fmaxf(acc[i][7] + bb[i], 0.0f);
        *(float4*)&Cb[(long)(ot + i) * P + ptA] = vA;
        *(float4*)&Cb[(long)(ot + i) * P + ptB] = vB;
    }
}

// ---------------------------------------------------------------------------
// Launch
// ---------------------------------------------------------------------------
extern "C" void kernel_launch(void* const* d_in, const int* in_sizes, int n_in,
                              void* d_out, int out_size)
{
    const float* unknown      = (const float*)d_in[0];
    const float* known        = (const float*)d_in[1];
    const float* unknow_feats = (const float*)d_in[2];
    const float* known_feats  = (const float*)d_in[3];
    const float* W1           = (const float*)d_in[4];
    const float* b1           = (const float*)d_in[5];
    const float* W2           = (const float*)d_in[6];
    const float* b2           = (const float*)d_in[7];
    float* out = (float*)d_out;

    void *pGt, *pH, *pIdx, *pWts;
    cudaGetSymbolAddress(&pGt,  g_Gt);
    cudaGetSymbolAddress(&pH,   g_h);
    cudaGetSymbolAddress(&pIdx, g_idx);
    cudaGetSymbolAddress(&pWts, g_wts);

    // 1) 3-NN + weights (1 thread per query — R1-proven)
    knn_kernel<<<dim3(NN / 256, BB), 256>>>(unknown, known, (int3*)pIdx, (float3*)pWts);

    // 2) Gt[b,m,o] = sum_c W1[o,c] * known_feats[b,c,m]  (c in [0,256)), (P,O) store
    gemm_po_kernel<<<dim3(MM / 128, H1_ / 64, BB), 256>>>(
        W1, C1_ + C2_, known_feats, (long)C2_ * MM,
        (float*)pGt, (long)MM * H1_, H1_, MM, C2_);

    // 3+4) h = relu( W1b @ unknow_feats + gather-interp(Gt) + b1 ), (O,P) store
    gemm_fused_kernel<<<dim3(NN / 128, H1_ / 64, BB), 256>>>(
        W1 + C2_, C1_ + C2_, unknow_feats, (long)C1_ * NN,
        (const float*)pGt, (const int3*)pIdx, (const float3*)pWts,
        b1, (float*)pH, H1_, NN, C1_);

    // 5) out = relu(W2 @ h + b2), (O,P) store
    gemm_op_kernel<<<dim3(NN / 128, H2_ / 64, BB), 256>>>(
        W2, H1_, (const float*)pH, (long)H1_ * NN,
        out, (long)H2_ * NN, b2, H2_, NN, H1_);
}